// round 10
// baseline (speedup 1.0000x reference)
#include <cuda_runtime.h>
#include <cstdint>
#include <math.h>

// ============================================================================
// libdevice-matching transcendentals
// ============================================================================
#if defined(__USE_FAST_MATH__)
__device__ __forceinline__ float xlogf(float x){ return (float)log((double)x); }
__device__ __forceinline__ float xlog1pf(float x){ return (float)log1p((double)x); }
__device__ __forceinline__ float xexpf(float x){ return (float)exp((double)x); }
#else
__device__ __forceinline__ float xlogf(float x){ return logf(x); }
__device__ __forceinline__ float xlog1pf(float x){ return log1pf(x); }
__device__ __forceinline__ float xexpf(float x){ return expf(x); }
#endif

// ============================================================================
// Threefry-2x32 (exact JAX partitionable replication)
// ============================================================================
#define TF_C 0x1BD11BDAu

struct U2 { uint32_t a, b; };

__device__ __forceinline__ uint32_t rotl32(uint32_t x, int r){
    return __funnelshift_l(x, x, r);
}

__device__ __forceinline__ U2 threefry(uint32_t k0, uint32_t k1, uint32_t x0, uint32_t x1){
    uint32_t k2 = k0 ^ k1 ^ TF_C;
    x0 += k0; x1 += k1;
#define TFR(r) { x0 += x1; x1 = rotl32(x1, (r)); x1 ^= x0; }
    TFR(13) TFR(15) TFR(26) TFR(6)
    x0 += k1; x1 += k2 + 1u;
    TFR(17) TFR(29) TFR(16) TFR(24)
    x0 += k2; x1 += k0 + 2u;
    TFR(13) TFR(15) TFR(26) TFR(6)
    x0 += k0; x1 += k1 + 3u;
    TFR(17) TFR(29) TFR(16) TFR(24)
    x0 += k1; x1 += k2 + 4u;
    TFR(13) TFR(15) TFR(26) TFR(6)
    x0 += k2; x1 += k0 + 5u;
#undef TFR
    U2 r; r.a = x0; r.b = x1; return r;
}

__device__ __forceinline__ uint32_t tf_bits(uint32_t k0, uint32_t k1, uint32_t idx){
    U2 o = threefry(k0, k1, 0u, idx);
    return o.a ^ o.b;
}

__device__ __forceinline__ float u01(uint32_t bits){
    return __uint_as_float((bits >> 9) | 0x3f800000u) - 1.0f;
}

// XLA ErfInv32 (Giles polynomial)
__device__ __forceinline__ float erfinv_xla(float x){
    float w = -xlog1pf(-x * x);
    float p;
    if (w < 5.0f){
        w = w - 2.5f;
        p = 2.81022636e-08f;
        p = fmaf(p, w, 3.43273939e-07f);
        p = fmaf(p, w, -3.5233877e-06f);
        p = fmaf(p, w, -4.39150654e-06f);
        p = fmaf(p, w, 0.00021858087f);
        p = fmaf(p, w, -0.00125372503f);
        p = fmaf(p, w, -0.00417768164f);
        p = fmaf(p, w, 0.246640727f);
        p = fmaf(p, w, 1.50140941f);
    } else {
        w = sqrtf(w) - 3.0f;
        p = -0.000200214257f;
        p = fmaf(p, w, 0.000100950558f);
        p = fmaf(p, w, 0.00134934322f);
        p = fmaf(p, w, -0.00367342844f);
        p = fmaf(p, w, 0.00573950773f);
        p = fmaf(p, w, -0.0076224613f);
        p = fmaf(p, w, 0.00943887047f);
        p = fmaf(p, w, 1.00167406f);
        p = fmaf(p, w, 2.83297682f);
    }
    return p * x;
}

// ============================================================================
// packed f32x2 helpers
// ============================================================================
__device__ __forceinline__ unsigned long long pk2(float x, float y){
    unsigned long long r;
    asm("mov.b64 %0, {%1, %2};" : "=l"(r) : "f"(x), "f"(y));
    return r;
}
__device__ __forceinline__ void fma2(unsigned long long& d, unsigned long long a, unsigned long long b){
    asm("fma.rn.f32x2 %0, %1, %2, %0;" : "+l"(d) : "l"(a), "l"(b));
}
__device__ __forceinline__ void add2(unsigned long long& d, unsigned long long a){
    asm("add.rn.f32x2 %0, %0, %1;" : "+l"(d) : "l"(a));
}
__device__ __forceinline__ float2 upk2(unsigned long long v){
    float2 r;
    asm("mov.b64 {%0, %1}, %2;" : "=f"(r.x), "=f"(r.y) : "l"(v));
    return r;
}

// ============================================================================
// Device scratch + constant weights (full W1 = 512x32 f32 = exactly 64 KB)
// ============================================================================
__device__ uint2 g_k1[64];
__device__ uint2 g_k2[64];
__device__ uint2 g_kv;
__device__ float g_norm[4194304];      // [B][32] raw normals (31 used)
__constant__ ulonglong2 c_W1[4096];    // [512][8] packed f32x2 pairs

// ============================================================================
// Kernel 1: RNG keys (partitionable semantics)
// ============================================================================
__global__ void k_setup(const int* __restrict__ seedp){
    int i = threadIdx.x;
    uint32_t s = (uint32_t)seedp[0];
    if (i < 50){
        U2 fk = threefry(0u, s, 0u, (uint32_t)i);
        U2 kw = threefry(fk.a, fk.b, 0u, 0u);
        U2 kr = threefry(fk.a, fk.b, 0u, 1u);
        g_k1[i] = make_uint2(kw.a, kw.b);
        g_k2[i] = make_uint2(kr.a, kr.b);
    } else if (i == 50){
        U2 kv = threefry(0u, s, 0u, 10000u);
        g_kv = make_uint2(kv.a, kv.b);
    }
}

// ============================================================================
// Kernel 2 (R4 proven): encode GEMM [B,512]x[512,33] -> mu (l2norm) + kappa
// ============================================================================
__global__ void __launch_bounds__(256, 2) k_gemm1(
    const float* __restrict__ h,
    const float* __restrict__ Wmu, const float* __restrict__ bmu,
    const float* __restrict__ Wk,  const float* __restrict__ bk,
    float* __restrict__ outp, int B)
{
    extern __shared__ float sm[];
    float* hs = sm;                  // 512 x 33
    float* Wt = sm + 512 * 33;       // 32 x 36

    const int tid  = threadIdx.x;
    const int row0 = blockIdx.x * 512;

    for (int idx = tid; idx < 32 * 36; idx += 256) Wt[idx] = 0.0f;

    unsigned long long a0[18], a1[18];
#pragma unroll
    for (int j = 0; j < 18; j++){ a0[j] = 0ull; a1[j] = 0ull; }

    const float4* h4 = (const float4*)h;

    for (int c = 0; c < 16; c++){
        __syncthreads();
        for (int idx = tid; idx < 1056; idx += 256){
            int j  = idx >> 5;
            int kk = idx & 31;
            float v = (j < 32) ? Wmu[j * 512 + c * 32 + kk] : Wk[c * 32 + kk];
            Wt[kk * 36 + j] = v;
        }
#pragma unroll
        for (int it = 0; it < 16; it++){
            int lin = tid + it * 256;
            int r = lin >> 3, q = lin & 7;
            float4 v = h4[(size_t)(row0 + r) * 128 + (size_t)(c * 8 + q)];
            float* dst = &hs[r * 33 + q * 4];
            dst[0] = v.x; dst[1] = v.y; dst[2] = v.z; dst[3] = v.w;
        }
        __syncthreads();

        const int b0 = tid * 33;
        const int b1 = (tid + 256) * 33;
#pragma unroll 2
        for (int kk = 0; kk < 32; kk++){
            float hv0 = hs[b0 + kk];
            float hv1 = hs[b1 + kk];
            unsigned long long h0 = pk2(hv0, hv0);
            unsigned long long h1 = pk2(hv1, hv1);
            const ulonglong2* wr = (const ulonglong2*)&Wt[kk * 36];
#pragma unroll
            for (int j = 0; j < 9; j++){
                ulonglong2 t = wr[j];
                fma2(a0[2 * j],     h0, t.x);
                fma2(a0[2 * j + 1], h0, t.y);
                fma2(a1[2 * j],     h1, t.x);
                fma2(a1[2 * j + 1], h1, t.y);
            }
        }
    }

#pragma unroll
    for (int rsel = 0; rsel < 2; rsel++){
        const int row = row0 + tid + rsel * 256;
        unsigned long long* ap = rsel ? a1 : a0;
        float acc[36];
#pragma unroll
        for (int j = 0; j < 18; j++){
            float2 t = upk2(ap[j]);
            acc[2 * j] = t.x; acc[2 * j + 1] = t.y;
        }
        float ss = 0.0f;
#pragma unroll
        for (int j = 0; j < 32; j++){
            acc[j] += bmu[j];
            ss = fmaf(acc[j], acc[j], ss);
        }
        float den = fmaxf(sqrtf(ss), 1e-12f);
        size_t muoff = (size_t)B * 7 + (size_t)row * 32;
#pragma unroll
        for (int j = 0; j < 32; j++) outp[muoff + j] = acc[j] / den;

        float x = __fadd_rn(acc[32], bk[0]);
        float sp = __fadd_rn(fmaxf(x, 0.0f), xlog1pf(xexpf(-fabsf(x))));
        outp[(size_t)B * 39 + row] = __fadd_rn(sp, 1.0f);
    }
}

// ============================================================================
// Kernel 3: normals — RNG index e = b*31+c, stored at stride 32
// ============================================================================
__global__ void __launch_bounds__(256) k_normals(int n){
    int e = blockIdx.x * 256 + threadIdx.x;
    if (e >= n) return;
    uint2 kv = g_kv;
    uint32_t bits = tf_bits(kv.x, kv.y, (uint32_t)e);
    float f = u01(bits);
    const float lo = -0.99999994f;
    float u = fmaxf(lo, __fadd_rn(__fmul_rn(f, 2.0f), lo));
    int b = e / 31, c = e - b * 31;
    g_norm[b * 32 + c] = __fmul_rn(1.41421356f, erfinv_xla(u));
}

// ============================================================================
// Kernel 4: FUSED Wood + Householder + MLP — 2 rows/thread, 128-thread CTAs,
// 3 CTAs/SM. W1 in __constant__ (shared by both rows), W2^T in smem.
// ============================================================================
__global__ void __launch_bounds__(128, 3) k_sampler(
    const float* __restrict__ W2, const float* __restrict__ b1,
    const float* __restrict__ b2,
    const float* __restrict__ W3, const float* __restrict__ b3,
    float* __restrict__ outp, int B)
{
    extern __shared__ float sm[];
    float* W2t = sm;                 // [512][32] transposed
    float* b1s = W2t + 16384;        // [512]
    float* b2s = b1s + 512;          // [32]
    float* W3s = b2s + 32;           // [7][32]
    float* b3s = W3s + 224;          // [8]
    uint2* sk1 = (uint2*)(b3s + 8);  // [50]
    uint2* sk2 = sk1 + 50;           // [50]

    const int tid = threadIdx.x;
    for (int i = tid; i < 16384; i += 128){
        int m = i >> 9, hh = i & 511;
        W2t[hh * 32 + m] = W2[i];
    }
    for (int i = tid; i < 512; i += 128) b1s[i] = b1[i];
    if (tid < 32)  b2s[tid] = b2[tid];
    if (tid < 8)   b3s[tid] = (tid < 7) ? b3[tid] : 0.0f;
    if (tid < 50)  sk1[tid] = g_k1[tid];
    else if (tid < 100) sk2[tid - 50] = g_k2[tid - 50];
    for (int i = tid; i < 224; i += 128) W3s[i] = W3[i];
    __syncthreads();

    const int r0 = blockIdx.x * 256 + tid;     // rows r0 and r0+128
    const int r1 = r0 + 128;

    const float kap0 = outp[(size_t)B * 39 + r0];
    const float kap1 = outp[(size_t)B * 39 + r1];

    // ---- Wood's rejection for both rows in one loop ----
    float w0 = 0.0f, w1 = 0.0f;
    bool d0 = false, d1 = false;
    for (int i = 0; i < 50; i++){
        if (__all_sync(0xffffffffu, d0 && d1)) break;
        uint2 K1 = sk1[i];
        uint2 K2 = sk2[i];
        if (!d0){
            float u1 = u01(tf_bits(K1.x, K1.y, (uint32_t)r0));
            float wc = __fsub_rn(__fmul_rn(2.0f, u1), 1.0f);
            float omw = fmaxf(__fsub_rn(1.0f, __fmul_rn(wc, wc)), 1e-38f);
            float logp = __fadd_rn(__fmul_rn(kap0, wc), __fmul_rn(14.5f, xlogf(omw)));
            float u2 = u01(tf_bits(K2.x, K2.y, (uint32_t)r0));
            float logr = xlogf(__fadd_rn(u2, 1e-38f));
            if (__fadd_rn(logr, kap0) <= logp){ w0 = wc; d0 = true; }
        }
        if (!d1){
            float u1 = u01(tf_bits(K1.x, K1.y, (uint32_t)r1));
            float wc = __fsub_rn(__fmul_rn(2.0f, u1), 1.0f);
            float omw = fmaxf(__fsub_rn(1.0f, __fmul_rn(wc, wc)), 1e-38f);
            float logp = __fadd_rn(__fmul_rn(kap1, wc), __fmul_rn(14.5f, xlogf(omw)));
            float u2 = u01(tf_bits(K2.x, K2.y, (uint32_t)r1));
            float logr = xlogf(__fadd_rn(u2, 1e-38f));
            if (__fadd_rn(logr, kap1) <= logp){ w1 = wc; d1 = true; }
        }
    }
    w0 = fminf(fmaxf(w0, -1.0f), 1.0f);
    w1 = fminf(fmaxf(w1, -1.0f), 1.0f);

    // ---- per-row prologue -> packed z vectors ----
    unsigned long long zpA[16], zpB[16];
#pragma unroll
    for (int rsel = 0; rsel < 2; rsel++){
        const int rr = rsel ? r1 : r0;
        const float w = rsel ? w1 : w0;
        unsigned long long* zp = rsel ? zpB : zpA;

        float z[32];
        const float4* nv = (const float4*)&g_norm[(size_t)rr * 32];
#pragma unroll
        for (int q = 0; q < 8; q++){
            float4 v = nv[q];
            z[q * 4 + 0] = v.x; z[q * 4 + 1] = v.y;
            z[q * 4 + 2] = v.z; z[q * 4 + 3] = v.w;
        }
        z[31] = 0.0f;
        float ssn = 0.0f;
#pragma unroll
        for (int c = 0; c < 31; c++) ssn = fmaf(z[c], z[c], ssn);
        float den = fmaxf(sqrtf(ssn), 1e-12f);
        float st  = sqrtf(fmaxf(__fsub_rn(1.0f, __fmul_rn(w, w)), 1e-38f));
        float sc  = st / den;
#pragma unroll
        for (int c = 0; c < 31; c++) z[c] *= sc;
        z[31] = w;

        // Householder
        const size_t muoff = (size_t)B * 7 + (size_t)rr * 32;
        float uh[32];
        float ssu = 0.0f;
        const float4* mu4 = (const float4*)(outp + muoff);
#pragma unroll
        for (int q = 0; q < 8; q++){
            float4 m = mu4[q];
            float t0 = ((q * 4 + 0) == 31 ? 1.0f : 0.0f) - m.x;
            float t1 = ((q * 4 + 1) == 31 ? 1.0f : 0.0f) - m.y;
            float t2 = ((q * 4 + 2) == 31 ? 1.0f : 0.0f) - m.z;
            float t3 = ((q * 4 + 3) == 31 ? 1.0f : 0.0f) - m.w;
            uh[q * 4 + 0] = t0; uh[q * 4 + 1] = t1;
            uh[q * 4 + 2] = t2; uh[q * 4 + 3] = t3;
            ssu = fmaf(t0, t0, ssu); ssu = fmaf(t1, t1, ssu);
            ssu = fmaf(t2, t2, ssu); ssu = fmaf(t3, t3, ssu);
        }
        float inv = 1.0f / fmaxf(sqrtf(ssu), 1e-12f);
        float dot = 0.0f;
#pragma unroll
        for (int j = 0; j < 32; j++){
            uh[j] *= inv;
            dot = fmaf(z[j], uh[j], dot);
        }
        float d2 = 2.0f * dot;
#pragma unroll
        for (int j = 0; j < 32; j++) z[j] = fmaf(-d2, uh[j], z[j]);

#pragma unroll
        for (int l = 0; l < 16; l++) zp[l] = pk2(z[2 * l], z[2 * l + 1]);
    }

    // ---- MLP: weights loaded once per hh, used by BOTH rows ----
    unsigned long long x2pA[16], x2pB[16];
#pragma unroll
    for (int m = 0; m < 16; m++){
        unsigned long long bb = pk2(b2s[2 * m], b2s[2 * m + 1]);
        x2pA[m] = bb; x2pB[m] = bb;
    }

#pragma unroll 2
    for (int hh = 0; hh < 512; hh++){
        const ulonglong2* wa = &c_W1[hh << 3];
        unsigned long long aA0 = 0ull, aA1 = 0ull, aB0 = 0ull, aB1 = 0ull;
#pragma unroll
        for (int j = 0; j < 4; j++){
            ulonglong2 ta = wa[j];
            ulonglong2 tb = wa[j + 4];
            fma2(aA0, zpA[2 * j],     ta.x);
            fma2(aA1, zpA[2 * j + 1], ta.y);
            fma2(aA0, zpA[2 * j + 8], tb.x);
            fma2(aA1, zpA[2 * j + 9], tb.y);
            fma2(aB0, zpB[2 * j],     ta.x);
            fma2(aB1, zpB[2 * j + 1], ta.y);
            fma2(aB0, zpB[2 * j + 8], tb.x);
            fma2(aB1, zpB[2 * j + 9], tb.y);
        }
        add2(aA0, aA1);
        add2(aB0, aB1);
        float2 rA = upk2(aA0), rB = upk2(aB0);
        float aA = fmaxf(b1s[hh] + (rA.x + rA.y), 0.0f);
        float aB = fmaxf(b1s[hh] + (rB.x + rB.y), 0.0f);

        unsigned long long aaA = pk2(aA, aA);
        unsigned long long aaB = pk2(aB, aB);
        const ulonglong2* w2r = (const ulonglong2*)&W2t[hh * 32];
#pragma unroll
        for (int m4 = 0; m4 < 8; m4++){
            ulonglong2 t = w2r[m4];
            fma2(x2pA[2 * m4],     aaA, t.x);
            fma2(x2pA[2 * m4 + 1], aaA, t.y);
            fma2(x2pB[2 * m4],     aaB, t.x);
            fma2(x2pB[2 * m4 + 1], aaB, t.y);
        }
    }

    // ---- relu + head + store, per row ----
#pragma unroll
    for (int rsel = 0; rsel < 2; rsel++){
        const int rr = rsel ? r1 : r0;
        unsigned long long* x2p = rsel ? x2pB : x2pA;
        unsigned long long xr[16];
#pragma unroll
        for (int m = 0; m < 16; m++){
            float2 t = upk2(x2p[m]);
            xr[m] = pk2(fmaxf(t.x, 0.0f), fmaxf(t.y, 0.0f));
        }
        float outv[7];
#pragma unroll
        for (int o = 0; o < 7; o++){
            unsigned long long acc = 0ull;
            const ulonglong2* w3r = (const ulonglong2*)&W3s[o * 32];
#pragma unroll
            for (int m4 = 0; m4 < 8; m4++){
                ulonglong2 t = w3r[m4];
                fma2(acc, xr[2 * m4],     t.x);
                fma2(acc, xr[2 * m4 + 1], t.y);
            }
            float2 rr2 = upk2(acc);
            outv[o] = b3s[o] + (rr2.x + rr2.y);
        }
#pragma unroll
        for (int o = 0; o < 7; o++) outp[(size_t)rr * 7 + o] = outv[o];
    }
}

// ============================================================================
// launch
// ============================================================================
extern "C" void kernel_launch(void* const* d_in, const int* in_sizes, int n_in,
                              void* d_out, int out_size)
{
    const float* h    = (const float*)d_in[0];
    const float* Wmu  = (const float*)d_in[1];
    const float* bmu  = (const float*)d_in[2];
    const float* Wk   = (const float*)d_in[3];
    const float* bk   = (const float*)d_in[4];
    const float* W1   = (const float*)d_in[5];
    const float* b1   = (const float*)d_in[6];
    const float* W2   = (const float*)d_in[7];
    const float* b2   = (const float*)d_in[8];
    const float* W3   = (const float*)d_in[9];
    const float* b3   = (const float*)d_in[10];
    const int*   seed = (const int*)d_in[11];

    const int F = 512;
    const int B = in_sizes[0] / F;          // 131072
    float* outp = (float*)d_out;

    const int smem2 = (512 * 33 + 32 * 36) * 4;                    // 72,192
    const int smem4 = (16384 + 512 + 32 + 224 + 8) * 4 + 100 * 8;  // 69,440
    cudaFuncSetAttribute(k_gemm1,   cudaFuncAttributeMaxDynamicSharedMemorySize, smem2);
    cudaFuncSetAttribute(k_sampler, cudaFuncAttributeMaxDynamicSharedMemorySize, smem4);

    // W1 -> constant bank (raw byte copy; layout matches packed f32x2 pairs)
    cudaMemcpyToSymbolAsync(c_W1, W1, 16384 * sizeof(float), 0,
                            cudaMemcpyDeviceToDevice, 0);

    k_setup<<<1, 64>>>(seed);

    k_gemm1<<<B / 512, 256, smem2>>>(h, Wmu, bmu, Wk, bk, outp, B);

    int n = B * 31;
    k_normals<<<(n + 255) / 256, 256>>>(n);

    k_sampler<<<B / 256, 128, smem4>>>(W2, b1, b2, W3, b3, outp, B);
}

// round 11
// speedup vs baseline: 1.6632x; 1.6632x over previous
#include <cuda_runtime.h>
#include <cstdint>
#include <math.h>

// ============================================================================
// libdevice-matching transcendentals
// ============================================================================
#if defined(__USE_FAST_MATH__)
__device__ __forceinline__ float xlogf(float x){ return (float)log((double)x); }
__device__ __forceinline__ float xlog1pf(float x){ return (float)log1p((double)x); }
__device__ __forceinline__ float xexpf(float x){ return (float)exp((double)x); }
#else
__device__ __forceinline__ float xlogf(float x){ return logf(x); }
__device__ __forceinline__ float xlog1pf(float x){ return log1pf(x); }
__device__ __forceinline__ float xexpf(float x){ return expf(x); }
#endif

// ============================================================================
// Threefry-2x32 (exact JAX partitionable replication)
// ============================================================================
#define TF_C 0x1BD11BDAu

struct U2 { uint32_t a, b; };

__device__ __forceinline__ uint32_t rotl32(uint32_t x, int r){
    return __funnelshift_l(x, x, r);
}

__device__ __forceinline__ U2 threefry(uint32_t k0, uint32_t k1, uint32_t x0, uint32_t x1){
    uint32_t k2 = k0 ^ k1 ^ TF_C;
    x0 += k0; x1 += k1;
#define TFR(r) { x0 += x1; x1 = rotl32(x1, (r)); x1 ^= x0; }
    TFR(13) TFR(15) TFR(26) TFR(6)
    x0 += k1; x1 += k2 + 1u;
    TFR(17) TFR(29) TFR(16) TFR(24)
    x0 += k2; x1 += k0 + 2u;
    TFR(13) TFR(15) TFR(26) TFR(6)
    x0 += k0; x1 += k1 + 3u;
    TFR(17) TFR(29) TFR(16) TFR(24)
    x0 += k1; x1 += k2 + 4u;
    TFR(13) TFR(15) TFR(26) TFR(6)
    x0 += k2; x1 += k0 + 5u;
#undef TFR
    U2 r; r.a = x0; r.b = x1; return r;
}

__device__ __forceinline__ uint32_t tf_bits(uint32_t k0, uint32_t k1, uint32_t idx){
    U2 o = threefry(k0, k1, 0u, idx);
    return o.a ^ o.b;
}

__device__ __forceinline__ float u01(uint32_t bits){
    return __uint_as_float((bits >> 9) | 0x3f800000u) - 1.0f;
}

// XLA ErfInv32 (Giles polynomial)
__device__ __forceinline__ float erfinv_xla(float x){
    float w = -xlog1pf(-x * x);
    float p;
    if (w < 5.0f){
        w = w - 2.5f;
        p = 2.81022636e-08f;
        p = fmaf(p, w, 3.43273939e-07f);
        p = fmaf(p, w, -3.5233877e-06f);
        p = fmaf(p, w, -4.39150654e-06f);
        p = fmaf(p, w, 0.00021858087f);
        p = fmaf(p, w, -0.00125372503f);
        p = fmaf(p, w, -0.00417768164f);
        p = fmaf(p, w, 0.246640727f);
        p = fmaf(p, w, 1.50140941f);
    } else {
        w = sqrtf(w) - 3.0f;
        p = -0.000200214257f;
        p = fmaf(p, w, 0.000100950558f);
        p = fmaf(p, w, 0.00134934322f);
        p = fmaf(p, w, -0.00367342844f);
        p = fmaf(p, w, 0.00573950773f);
        p = fmaf(p, w, -0.0076224613f);
        p = fmaf(p, w, 0.00943887047f);
        p = fmaf(p, w, 1.00167406f);
        p = fmaf(p, w, 2.83297682f);
    }
    return p * x;
}

// ============================================================================
// packed f32x2 helpers (gemm1 mainloop)
// ============================================================================
__device__ __forceinline__ unsigned long long pk2(float x, float y){
    unsigned long long r;
    asm("mov.b64 %0, {%1, %2};" : "=l"(r) : "f"(x), "f"(y));
    return r;
}
__device__ __forceinline__ void fma2(unsigned long long& d, unsigned long long a, unsigned long long b){
    asm("fma.rn.f32x2 %0, %1, %2, %0;" : "+l"(d) : "l"(a), "l"(b));
}
__device__ __forceinline__ float2 upk2(unsigned long long v){
    float2 r;
    asm("mov.b64 {%0, %1}, %2;" : "=f"(r.x), "=f"(r.y) : "l"(v));
    return r;
}

// ============================================================================
// tf32 helpers
// ============================================================================
__device__ __forceinline__ uint32_t f2tf32(float x){
    uint32_t r;
    asm("cvt.rna.tf32.f32 %0, %1;" : "=r"(r) : "f"(x));
    return r;
}

__device__ __forceinline__ void mma_tf32(
    float& c0, float& c1, float& c2, float& c3,
    uint32_t a0, uint32_t a1, uint32_t a2, uint32_t a3,
    uint32_t b0, uint32_t b1)
{
    asm volatile(
        "mma.sync.aligned.m16n8k8.row.col.f32.tf32.tf32.f32 "
        "{%0,%1,%2,%3},{%4,%5,%6,%7},{%8,%9},{%0,%1,%2,%3};"
        : "+f"(c0), "+f"(c1), "+f"(c2), "+f"(c3)
        : "r"(a0), "r"(a1), "r"(a2), "r"(a3), "r"(b0), "r"(b1));
}

// Convert a D fragment (m16n8: c0/c1 = n-pair cols 2t,2t+1) of an 8-col chunk
// into an A fragment (m16k8: cols t and t+4) via intra-quad shuffles.
__device__ __forceinline__ void dfrag_to_afrag(
    uint32_t x0, uint32_t x1, uint32_t x2, uint32_t x3,
    uint32_t& a0, uint32_t& a1, uint32_t& a2, uint32_t& a3, int lane)
{
    int t = lane & 3;
    int srcA = (lane & ~3) | (t >> 1);
    int srcB = srcA + 2;
    uint32_t s0 = __shfl_sync(0xffffffffu, x0, srcA);
    uint32_t s1 = __shfl_sync(0xffffffffu, x1, srcA);
    uint32_t s2 = __shfl_sync(0xffffffffu, x0, srcB);
    uint32_t s3 = __shfl_sync(0xffffffffu, x1, srcB);
    a0 = (t & 1) ? s1 : s0;
    a2 = (t & 1) ? s3 : s2;
    uint32_t u0 = __shfl_sync(0xffffffffu, x2, srcA);
    uint32_t u1 = __shfl_sync(0xffffffffu, x3, srcA);
    uint32_t u2 = __shfl_sync(0xffffffffu, x2, srcB);
    uint32_t u3 = __shfl_sync(0xffffffffu, x3, srcB);
    a1 = (t & 1) ? u1 : u0;
    a3 = (t & 1) ? u3 : u2;
}

// ============================================================================
// Device scratch
// ============================================================================
__device__ uint2 g_k1[64];
__device__ uint2 g_k2[64];
__device__ uint2 g_kv;
__device__ uint32_t g_zf[4194304];   // z in tf32 A-fragment layout, 16MB
__device__ uint32_t g_w1f[16384];    // W1 B-fragments (tf32 bits)
__device__ uint32_t g_w2f[16384];    // W2 B-fragments
__device__ uint32_t g_w3f[256];      // W3 B-fragments (col 7 zero)

// ============================================================================
// Kernel 1: RNG keys (partitionable semantics)
// ============================================================================
__global__ void k_setup(const int* __restrict__ seedp){
    int i = threadIdx.x;
    uint32_t s = (uint32_t)seedp[0];
    if (i < 50){
        U2 fk = threefry(0u, s, 0u, (uint32_t)i);
        U2 kw = threefry(fk.a, fk.b, 0u, 0u);
        U2 kr = threefry(fk.a, fk.b, 0u, 1u);
        g_k1[i] = make_uint2(kw.a, kw.b);
        g_k2[i] = make_uint2(kr.a, kr.b);
    } else if (i == 50){
        U2 kv = threefry(0u, s, 0u, 10000u);
        g_kv = make_uint2(kv.a, kv.b);
    }
}

// ============================================================================
// Kernel 1b: pack weights into tf32 B-fragments
// B-frag layout (m16n8k8, row.col): b0 = B[tig][g], b1 = B[tig+4][g]
// ============================================================================
__global__ void k_packw(const float* __restrict__ W1,
                        const float* __restrict__ W2,
                        const float* __restrict__ W3){
    int j = blockIdx.x * 256 + threadIdx.x;
    if (j < 16384){
        // w1f: ((nt*4+kc)*32+lane)*2+p ; B = W1^T (K=32 x N=512)
        int p = j & 1, lane = (j >> 1) & 31, kc = (j >> 6) & 3, nt = j >> 8;
        int g = lane >> 2, t = lane & 3;
        g_w1f[j] = f2tf32(W1[(nt * 8 + g) * 32 + kc * 8 + t + 4 * p]);
    } else if (j < 32768){
        // w2f: ((nt2*64+kc2)*32+lane)*2+p ; B = W2^T (K=512 x N=32)
        int j2 = j - 16384;
        int p = j2 & 1, lane = (j2 >> 1) & 31, kc2 = (j2 >> 6) & 63, nt2 = j2 >> 12;
        int g = lane >> 2, t = lane & 3;
        g_w2f[j2] = f2tf32(W2[(nt2 * 8 + g) * 512 + kc2 * 8 + t + 4 * p]);
    } else if (j < 33024){
        // w3f: (kc*32+lane)*2+p ; B = W3^T (K=32 x N=8, col 7 zero)
        int j3 = j - 32768;
        int p = j3 & 1, lane = (j3 >> 1) & 31, kc = (j3 >> 6) & 3;
        int g = lane >> 2, t = lane & 3;
        g_w3f[j3] = (g < 7) ? f2tf32(W3[g * 32 + kc * 8 + t + 4 * p]) : 0u;
    }
}

// ============================================================================
// Kernel 2: FUSED encode GEMM + normals + Wood + Householder (R7 proven)
// stores z pre-converted to tf32 in A-fragment layout.
// ============================================================================
__global__ void __launch_bounds__(256, 2) k_fused1(
    const float* __restrict__ h,
    const float* __restrict__ Wmu, const float* __restrict__ bmu,
    const float* __restrict__ Wk,  const float* __restrict__ bk,
    float* __restrict__ outp, int B)
{
    extern __shared__ float sm[];
    float* hs = sm;                        // 512 x 33
    float* Wt = sm + 512 * 33;             // 32 x 36
    uint2* sk1 = (uint2*)(Wt + 32 * 36);   // [50]
    uint2* sk2 = sk1 + 50;                 // [50]

    const int tid  = threadIdx.x;
    const int row0 = blockIdx.x * 512;

    if (tid < 50)       sk1[tid] = g_k1[tid];
    else if (tid < 100) sk2[tid - 50] = g_k2[tid - 50];
    for (int idx = tid; idx < 32 * 36; idx += 256) Wt[idx] = 0.0f;

    unsigned long long a0[18], a1[18];
#pragma unroll
    for (int j = 0; j < 18; j++){ a0[j] = 0ull; a1[j] = 0ull; }

    const float4* h4 = (const float4*)h;

    for (int c = 0; c < 16; c++){
        __syncthreads();
        for (int idx = tid; idx < 1056; idx += 256){
            int j  = idx >> 5;
            int kk = idx & 31;
            float v = (j < 32) ? Wmu[j * 512 + c * 32 + kk] : Wk[c * 32 + kk];
            Wt[kk * 36 + j] = v;
        }
#pragma unroll
        for (int it = 0; it < 16; it++){
            int lin = tid + it * 256;
            int r = lin >> 3, q = lin & 7;
            float4 v = h4[(size_t)(row0 + r) * 128 + (size_t)(c * 8 + q)];
            float* dst = &hs[r * 33 + q * 4];
            dst[0] = v.x; dst[1] = v.y; dst[2] = v.z; dst[3] = v.w;
        }
        __syncthreads();

        const int b0 = tid * 33;
        const int b1 = (tid + 256) * 33;
#pragma unroll 2
        for (int kk = 0; kk < 32; kk++){
            float hv0 = hs[b0 + kk];
            float hv1 = hs[b1 + kk];
            unsigned long long h0 = pk2(hv0, hv0);
            unsigned long long h1 = pk2(hv1, hv1);
            const ulonglong2* wr = (const ulonglong2*)&Wt[kk * 36];
#pragma unroll
            for (int j = 0; j < 9; j++){
                ulonglong2 t = wr[j];
                fma2(a0[2 * j],     h0, t.x);
                fma2(a0[2 * j + 1], h0, t.y);
                fma2(a1[2 * j],     h1, t.x);
                fma2(a1[2 * j + 1], h1, t.y);
            }
        }
    }

    // epilogue: mu + kappa for both rows
    float kap[2];
#pragma unroll
    for (int rsel = 0; rsel < 2; rsel++){
        const int row = row0 + tid + rsel * 256;
        unsigned long long* ap = rsel ? a1 : a0;
        float acc[36];
#pragma unroll
        for (int j = 0; j < 18; j++){
            float2 t = upk2(ap[j]);
            acc[2 * j] = t.x; acc[2 * j + 1] = t.y;
        }
        float ss = 0.0f;
#pragma unroll
        for (int j = 0; j < 32; j++){
            acc[j] += bmu[j];
            ss = fmaf(acc[j], acc[j], ss);
        }
        float den = fmaxf(sqrtf(ss), 1e-12f);
        size_t muoff = (size_t)B * 7 + (size_t)row * 32;
#pragma unroll
        for (int j = 0; j < 32; j++) outp[muoff + j] = acc[j] / den;

        float x = __fadd_rn(acc[32], bk[0]);
        float sp = __fadd_rn(fmaxf(x, 0.0f), xlog1pf(xexpf(-fabsf(x))));
        kap[rsel] = __fadd_rn(sp, 1.0f);
        outp[(size_t)B * 39 + row] = kap[rsel];
    }

    // per-row: normals -> Wood -> Householder -> z (fragment store)
    const uint2 kv = g_kv;
#pragma unroll 1
    for (int rsel = 0; rsel < 2; rsel++){
        const int row = row0 + tid + rsel * 256;
        const uint32_t ub = (uint32_t)row;
        const float kappa = kap[rsel];

        float z[32];
#pragma unroll 1
        for (int c = 0; c < 31; c++){
            uint32_t bits = tf_bits(kv.x, kv.y, (uint32_t)(row * 31 + c));
            float f = u01(bits);
            const float lo = -0.99999994f;
            float u = fmaxf(lo, __fadd_rn(__fmul_rn(f, 2.0f), lo));
            z[c] = __fmul_rn(1.41421356f, erfinv_xla(u));
        }

        // Wood's rejection (exact f32 op order)
        float w = 0.0f;
        bool done = false;
        for (int i = 0; i < 50; i++){
            if (__all_sync(0xffffffffu, done)) break;
            if (!done){
                uint2 K1 = sk1[i];
                float u1 = u01(tf_bits(K1.x, K1.y, ub));
                float wc = __fsub_rn(__fmul_rn(2.0f, u1), 1.0f);
                float omw = fmaxf(__fsub_rn(1.0f, __fmul_rn(wc, wc)), 1e-38f);
                float logp = __fadd_rn(__fmul_rn(kappa, wc), __fmul_rn(14.5f, xlogf(omw)));
                uint2 K2 = sk2[i];
                float u2 = u01(tf_bits(K2.x, K2.y, ub));
                float logr = xlogf(__fadd_rn(u2, 1e-38f));
                if (__fadd_rn(logr, kappa) <= logp){ w = wc; done = true; }
            }
        }
        w = fminf(fmaxf(w, -1.0f), 1.0f);

        // z_tilde
        {
            float ssn = 0.0f;
#pragma unroll
            for (int c = 0; c < 31; c++) ssn = fmaf(z[c], z[c], ssn);
            float den = fmaxf(sqrtf(ssn), 1e-12f);
            float st  = sqrtf(fmaxf(__fsub_rn(1.0f, __fmul_rn(w, w)), 1e-38f));
            float sc  = st / den;
#pragma unroll
            for (int c = 0; c < 31; c++) z[c] *= sc;
            z[31] = w;
        }

        // Householder
        {
            const size_t muoff = (size_t)B * 7 + (size_t)row * 32;
            float uh[32];
            float ssu = 0.0f;
            const float4* mu4 = (const float4*)(outp + muoff);
#pragma unroll
            for (int q = 0; q < 8; q++){
                float4 m = mu4[q];
                float t0 = ((q * 4 + 0) == 31 ? 1.0f : 0.0f) - m.x;
                float t1 = ((q * 4 + 1) == 31 ? 1.0f : 0.0f) - m.y;
                float t2 = ((q * 4 + 2) == 31 ? 1.0f : 0.0f) - m.z;
                float t3 = ((q * 4 + 3) == 31 ? 1.0f : 0.0f) - m.w;
                uh[q * 4 + 0] = t0; uh[q * 4 + 1] = t1;
                uh[q * 4 + 2] = t2; uh[q * 4 + 3] = t3;
                ssu = fmaf(t0, t0, ssu); ssu = fmaf(t1, t1, ssu);
                ssu = fmaf(t2, t2, ssu); ssu = fmaf(t3, t3, ssu);
            }
            float inv = 1.0f / fmaxf(sqrtf(ssu), 1e-12f);
            float dot = 0.0f;
#pragma unroll
            for (int j = 0; j < 32; j++){
                uh[j] *= inv;
                dot = fmaf(z[j], uh[j], dot);
            }
            float d2 = 2.0f * dot;
#pragma unroll
            for (int j = 0; j < 32; j++) z[j] = fmaf(-d2, uh[j], z[j]);
        }

        // store z as tf32 in A-fragment order:
        // a_i at (tile, kc, lane=g*4+t): i0=A[g][kc8+t], i1=A[g+8][kc8+t],
        //                                i2=A[g][kc8+t+4], i3=A[g+8][kc8+t+4]
        {
            const int tIdx = row >> 4;
            const int lr   = row & 15;
            const int gg   = lr & 7;
            const int hhp  = (lr >> 3) & 1;
#pragma unroll
            for (int kc = 0; kc < 4; kc++){
#pragma unroll
                for (int t = 0; t < 4; t++){
                    size_t base = ((size_t)(tIdx * 4 + kc) * 32 + (gg * 4 + t)) * 4;
                    g_zf[base + hhp]     = f2tf32(z[kc * 8 + t]);
                    g_zf[base + 2 + hhp] = f2tf32(z[kc * 8 + t + 4]);
                }
            }
        }
    }
}

// ============================================================================
// Kernel 3: tensor-core MLP. Persistent: grid=148, 8 warps/CTA, 16 rows/warp.
// relu(z@W1^T+b1) -> relu(@W2^T+b2) -> @W3^T+b3, tf32 mma, fp32 accum.
// ============================================================================
__global__ void __launch_bounds__(256) k_mlp_tc(
    const float* __restrict__ b1, const float* __restrict__ b2,
    const float* __restrict__ b3,
    float* __restrict__ outp, int B, int nTiles)
{
    extern __shared__ char smraw[];
    uint32_t* w1s = (uint32_t*)smraw;        // 16384
    uint32_t* w2s = w1s + 16384;             // 16384
    uint32_t* w3s = w2s + 16384;             // 256
    float* b1s = (float*)(w3s + 256);        // 512
    float* b2s = b1s + 512;                  // 32
    float* b3s = b2s + 32;                   // 8

    const int tid = threadIdx.x;
    {
        const uint4* s1 = (const uint4*)g_w1f;
        const uint4* s2 = (const uint4*)g_w2f;
        uint4* d1 = (uint4*)w1s;
        uint4* d2 = (uint4*)w2s;
        for (int i = tid; i < 4096; i += 256){ d1[i] = s1[i]; d2[i] = s2[i]; }
        if (tid < 64) ((uint4*)w3s)[tid] = ((const uint4*)g_w3f)[tid];
        for (int i = tid; i < 512; i += 256) b1s[i] = b1[i];
        if (tid < 32) b2s[tid] = b2[tid];
        if (tid < 8)  b3s[tid] = (tid < 7) ? b3[tid] : 0.0f;
    }
    __syncthreads();

    const int warp = tid >> 5;
    const int lane = tid & 31;
    const int g = lane >> 2;
    const int t = lane & 3;

    for (int tl = blockIdx.x * 8 + warp; tl < nTiles; tl += 148 * 8){
        const int r0 = tl * 16;

        // load z A-fragments (coalesced LDG.128 per kc)
        uint32_t az[4][4];
        const uint4* zp = (const uint4*)&g_zf[(size_t)tl * 512];
#pragma unroll
        for (int kc = 0; kc < 4; kc++){
            uint4 v = zp[kc * 32 + lane];
            az[kc][0] = v.x; az[kc][1] = v.y; az[kc][2] = v.z; az[kc][3] = v.w;
        }

        // layer-2 accumulators (4 n-tiles), bias-initialized
        float a2[4][4];
#pragma unroll
        for (int n2 = 0; n2 < 4; n2++){
            float bb0 = b2s[n2 * 8 + 2 * t];
            float bb1 = b2s[n2 * 8 + 2 * t + 1];
            a2[n2][0] = bb0; a2[n2][1] = bb1; a2[n2][2] = bb0; a2[n2][3] = bb1;
        }

        // stream hidden chunks: layer1 (4 mma) -> relu -> frag-convert -> layer2 (4 mma)
        for (int nt = 0; nt < 64; nt++){
            float c0 = b1s[nt * 8 + 2 * t];
            float c1 = b1s[nt * 8 + 2 * t + 1];
            float c2 = c0, c3 = c1;
            const uint2* w1p = (const uint2*)w1s + (nt * 4) * 32 + lane;
#pragma unroll
            for (int kc = 0; kc < 4; kc++){
                uint2 bb = w1p[kc * 32];
                mma_tf32(c0, c1, c2, c3,
                         az[kc][0], az[kc][1], az[kc][2], az[kc][3], bb.x, bb.y);
            }
            // relu + tf32
            uint32_t x0 = f2tf32(fmaxf(c0, 0.0f));
            uint32_t x1 = f2tf32(fmaxf(c1, 0.0f));
            uint32_t x2 = f2tf32(fmaxf(c2, 0.0f));
            uint32_t x3 = f2tf32(fmaxf(c3, 0.0f));
            uint32_t aa0, aa1, aa2, aa3;
            dfrag_to_afrag(x0, x1, x2, x3, aa0, aa1, aa2, aa3, lane);

            const uint2* w2p = (const uint2*)w2s + nt * 32 + lane;
#pragma unroll
            for (int n2 = 0; n2 < 4; n2++){
                uint2 bb = w2p[n2 * 64 * 32];
                mma_tf32(a2[n2][0], a2[n2][1], a2[n2][2], a2[n2][3],
                         aa0, aa1, aa2, aa3, bb.x, bb.y);
            }
        }

        // head: relu(x2) -> A-frags -> 4 mma with W3 frags
        float h0 = b3s[2 * t];
        float h1 = b3s[2 * t + 1];
        float h2 = h0, h3 = h1;
#pragma unroll
        for (int n2 = 0; n2 < 4; n2++){
            uint32_t x0 = f2tf32(fmaxf(a2[n2][0], 0.0f));
            uint32_t x1 = f2tf32(fmaxf(a2[n2][1], 0.0f));
            uint32_t x2 = f2tf32(fmaxf(a2[n2][2], 0.0f));
            uint32_t x3 = f2tf32(fmaxf(a2[n2][3], 0.0f));
            uint32_t aa0, aa1, aa2, aa3;
            dfrag_to_afrag(x0, x1, x2, x3, aa0, aa1, aa2, aa3, lane);
            uint2 bb = *((const uint2*)w3s + n2 * 32 + lane);
            mma_tf32(h0, h1, h2, h3, aa0, aa1, aa2, aa3, bb.x, bb.y);
        }

        // store out rows (cols 2t, 2t+1; skip col 7)
        const int rA = r0 + g;
        const int rB = rA + 8;
        outp[(size_t)rA * 7 + 2 * t] = h0;
        outp[(size_t)rB * 7 + 2 * t] = h2;
        if (t < 3){
            outp[(size_t)rA * 7 + 2 * t + 1] = h1;
            outp[(size_t)rB * 7 + 2 * t + 1] = h3;
        }
    }
}

// ============================================================================
// launch
// ============================================================================
extern "C" void kernel_launch(void* const* d_in, const int* in_sizes, int n_in,
                              void* d_out, int out_size)
{
    const float* h    = (const float*)d_in[0];
    const float* Wmu  = (const float*)d_in[1];
    const float* bmu  = (const float*)d_in[2];
    const float* Wk   = (const float*)d_in[3];
    const float* bk   = (const float*)d_in[4];
    const float* W1   = (const float*)d_in[5];
    const float* b1   = (const float*)d_in[6];
    const float* W2   = (const float*)d_in[7];
    const float* b2   = (const float*)d_in[8];
    const float* W3   = (const float*)d_in[9];
    const float* b3   = (const float*)d_in[10];
    const int*   seed = (const int*)d_in[11];

    const int F = 512;
    const int B = in_sizes[0] / F;          // 131072
    float* outp = (float*)d_out;

    const int smem1 = (512 * 33 + 32 * 36) * 4 + 100 * 8;          // 72,992
    const int smemT = (16384 + 16384 + 256) * 4 + (512 + 32 + 8) * 4; // 134,304
    cudaFuncSetAttribute(k_fused1, cudaFuncAttributeMaxDynamicSharedMemorySize, smem1);
    cudaFuncSetAttribute(k_mlp_tc, cudaFuncAttributeMaxDynamicSharedMemorySize, smemT);

    k_setup<<<1, 64>>>(seed);
    k_packw<<<129, 256>>>(W1, W2, W3);

    k_fused1<<<B / 512, 256, smem1>>>(h, Wmu, bmu, Wk, bk, outp, B);

    k_mlp_tc<<<148, 256, smemT>>>(b1, b2, b3, outp, B, B / 16);
}